// round 13
// baseline (speedup 1.0000x reference)
#include <cuda_runtime.h>
#include <math.h>

#define H 4096
#define EPS 1e-5f
#define ROWS_PER_BLOCK 8
#define NGEMV (5 * H / ROWS_PER_BLOCK)   // 2560, 512 blocks per z-part
#define EBLOCKS 16
#define ETHR 64                           // 16*64 = 1024 float4 = H/4

// Scratch + accumulators (no device allocation allowed).
__device__ __align__(16) float g_z[5 * H];
__device__ float g_sum[5]   = {0.f, 0.f, 0.f, 0.f, 0.f};
__device__ float g_sumsq[5] = {0.f, 0.f, 0.f, 0.f, 0.f};
__device__ float g_csum   = 0.f;
__device__ float g_csumsq = 0.f;
__device__ unsigned int g_ready = 0;   // gemv blocks completed
__device__ unsigned int g_cnt   = 0;   // epilogue blocks at cell-LN barrier
__device__ unsigned int g_done  = 0;   // epilogue blocks finished

__device__ __forceinline__ float sigmoidf_(float x) {
    return 1.0f / (1.0f + __expf(-x));
}
// tanh(x) = 1 - 2/(exp(2x)+1); saturates correctly at +/-inf.
__device__ __forceinline__ float tanhf_(float x) {
    return 1.0f - 2.0f / (__expf(2.0f * x) + 1.0f);
}

// ---------------------------------------------------------------------------
// Kernel 1: GEMV (exact R5 structure, best measured ~98.7us) + release signal.
// z[r] = dot(W[r, 0:2H], [h0;h1]); one warp per row; x staged in shared;
// W streamed with __ldcs. Per-part (sum,sumsq) via 2 atomics per block, then
// a single-thread device-scope release.
// ---------------------------------------------------------------------------
__global__ __launch_bounds__(256, 4)
void gemv_kernel(const float* __restrict__ h0,
                 const float* __restrict__ h1,
                 const float* __restrict__ W)
{
    __shared__ __align__(16) float xs[2 * H];
    __shared__ float rs[8], rq[8];

    const int tid = threadIdx.x;

    const float4* h0v = reinterpret_cast<const float4*>(h0);
    const float4* h1v = reinterpret_cast<const float4*>(h1);
    float4* xsv = reinterpret_cast<float4*>(xs);
    #pragma unroll
    for (int i = tid; i < H / 4; i += 256) {
        xsv[i]         = h0v[i];
        xsv[i + H / 4] = h1v[i];
    }
    __syncthreads();

    const int warp = tid >> 5;
    const int lane = tid & 31;
    const int row  = blockIdx.x * ROWS_PER_BLOCK + warp;

    const float4* wrow = reinterpret_cast<const float4*>(W + (size_t)row * (2 * H));

    float a0 = 0.f, a1 = 0.f, a2 = 0.f, a3 = 0.f;
    #pragma unroll 8
    for (int i = lane; i < (2 * H) / 4; i += 32) {
        float4 w = __ldcs(&wrow[i]);
        float4 x = xsv[i];
        a0 = fmaf(w.x, x.x, a0);
        a1 = fmaf(w.y, x.y, a1);
        a2 = fmaf(w.z, x.z, a2);
        a3 = fmaf(w.w, x.w, a3);
    }
    float s = (a0 + a1) + (a2 + a3);
    #pragma unroll
    for (int off = 16; off > 0; off >>= 1)
        s += __shfl_down_sync(0xffffffffu, s, off);

    if (lane == 0) {
        g_z[row] = s;
        rs[warp] = s;
        rq[warp] = s * s;
    }
    __syncthreads();

    if (tid == 0) {
        float bs = 0.f, bq = 0.f;
        #pragma unroll
        for (int w = 0; w < 8; w++) { bs += rs[w]; bq += rq[w]; }
        const int part = blockIdx.x >> 9;     // 512 blocks per part
        atomicAdd(&g_sum[part],   bs);
        atomicAdd(&g_sumsq[part], bq);
        __threadfence();                      // cumulative release of block's
        atomicAdd(&g_ready, 1u);              // z-stores + stat atomics
    }
}

// ---------------------------------------------------------------------------
// Kernel 2: epilogue, 16 CTAs x 64 threads, concurrent via graph fork on a
// HIGH-PRIORITY stream. Prefetches all GEMV-independent params into registers,
// spins on g_ready, then runs the z-dependent tail (L2-hot).
// ---------------------------------------------------------------------------
__global__ __launch_bounds__(ETHR, 1)
void epilogue_kernel(const float* __restrict__ c0,
                     const float* __restrict__ c1,
                     const float* __restrict__ ffio_g,
                     const float* __restrict__ ffio_b,
                     const float* __restrict__ u_g,
                     const float* __restrict__ u_b,
                     const float* __restrict__ c_g,
                     const float* __restrict__ c_b,
                     float* __restrict__ out)
{
    const int t    = threadIdx.x;   // 0..63
    const int warp = t >> 5;
    const int lane = t & 31;
    const int g    = blockIdx.x * ETHR + t;   // float4 index 0..1023

    __shared__ float red_s[2], red_q[2];
    __shared__ float s_mc, s_rc;

    // ---- Prefetch GEMV-independent inputs (overlaps the GEMV stream) -------
    float4 fg[4], fb[4];
    #pragma unroll
    for (int p = 0; p < 4; p++) {
        fg[p] = reinterpret_cast<const float4*>(ffio_g + p * H)[g];
        fb[p] = reinterpret_cast<const float4*>(ffio_b + p * H)[g];
    }
    float4 ugv = reinterpret_cast<const float4*>(u_g)[g];
    float4 ubv = reinterpret_cast<const float4*>(u_b)[g];
    float4 c0v = reinterpret_cast<const float4*>(c0)[g];
    float4 c1v = reinterpret_cast<const float4*>(c1)[g];
    float4 cgv = reinterpret_cast<const float4*>(c_g)[g];
    float4 cbv = reinterpret_cast<const float4*>(c_b)[g];

    // ---- Acquire: wait for all gemv blocks ---------------------------------
    if (t == 0) {
        while (*((volatile unsigned int*)&g_ready) < (unsigned)NGEMV)
            __nanosleep(64);
    }
    __syncthreads();
    __threadfence();    // acquire: subsequent reads see producers' writes

    float m5[5], r5[5];
    #pragma unroll
    for (int p = 0; p < 5; p++) {
        float mean = g_sum[p] * (1.0f / H);
        float var  = g_sumsq[p] * (1.0f / H) - mean * mean;
        m5[p] = mean;
        r5[p] = rsqrtf(var + EPS);
    }

    const float4* gz4 = reinterpret_cast<const float4*>(g_z);

    float v[5][4];
    #pragma unroll
    for (int p = 0; p < 5; p++) {
        float4 vv = gz4[p * (H / 4) + g];
        v[p][0] = vv.x; v[p][1] = vv.y; v[p][2] = vv.z; v[p][3] = vv.w;
    }

    float gate[4][4];
    #pragma unroll
    for (int p = 0; p < 4; p++) {
        float ga[4] = {fg[p].x, fg[p].y, fg[p].z, fg[p].w};
        float ba[4] = {fb[p].x, fb[p].y, fb[p].z, fb[p].w};
        float m = m5[p], r = r5[p];
        #pragma unroll
        for (int k = 0; k < 4; k++)
            gate[p][k] = sigmoidf_(fmaf((v[p][k] - m) * r, ga[k], ba[k]));
    }

    float uval[4];
    {
        float m = m5[4], r = r5[4];
        uval[0] = tanhf_(fmaf((v[4][0] - m) * r, ugv.x, ubv.x));
        uval[1] = tanhf_(fmaf((v[4][1] - m) * r, ugv.y, ubv.y));
        uval[2] = tanhf_(fmaf((v[4][2] - m) * r, ugv.z, ubv.z));
        uval[3] = tanhf_(fmaf((v[4][3] - m) * r, ugv.w, ubv.w));
    }

    float c0a[4] = {c0v.x, c0v.y, c0v.z, c0v.w};
    float c1a[4] = {c1v.x, c1v.y, c1v.z, c1v.w};

    float cell[4];
    #pragma unroll
    for (int k = 0; k < 4; k++)
        cell[k] = fmaf(gate[2][k], uval[k],
                  fmaf(gate[0][k], c0a[k], gate[1][k] * c1a[k]));

    // Block partial (sum, sumsq) of cell
    {
        float s = (cell[0] + cell[1]) + (cell[2] + cell[3]);
        float q = fmaf(cell[0], cell[0], fmaf(cell[1], cell[1],
                  fmaf(cell[2], cell[2], cell[3] * cell[3])));
        #pragma unroll
        for (int off = 16; off > 0; off >>= 1) {
            s += __shfl_down_sync(0xffffffffu, s, off);
            q += __shfl_down_sync(0xffffffffu, q, off);
        }
        if (lane == 0) { red_s[warp] = s; red_q[warp] = q; }
    }
    __syncthreads();

    // Cross-block (16 blocks) cell-LN reduction.
    if (t == 0) {
        atomicAdd(&g_csum,   red_s[0] + red_s[1]);
        atomicAdd(&g_csumsq, red_q[0] + red_q[1]);
        __threadfence();
        atomicAdd(&g_cnt, 1u);
        while (*((volatile unsigned int*)&g_cnt) < EBLOCKS)
            __nanosleep(32);
        __threadfence();
        float cs = atomicAdd(&g_csum,   0.0f);
        float cq = atomicAdd(&g_csumsq, 0.0f);
        float mean = cs * (1.0f / H);
        float var  = cq * (1.0f / H) - mean * mean;
        s_mc = mean;
        s_rc = rsqrtf(var + EPS);
    }
    __syncthreads();

    // Final LN on cell + outputs
    const float m = s_mc, r = s_rc;
    float cga[4] = {cgv.x, cgv.y, cgv.z, cgv.w};
    float cba[4] = {cbv.x, cbv.y, cbv.z, cbv.w};

    float4 hid, ncl;
    float nc[4], hd[4];
    #pragma unroll
    for (int k = 0; k < 4; k++) {
        nc[k] = fmaf((cell[k] - m) * r, cga[k], cba[k]);
        hd[k] = gate[3][k] * tanhf_(nc[k]);
    }
    hid.x = hd[0]; hid.y = hd[1]; hid.z = hd[2]; hid.w = hd[3];
    ncl.x = nc[0]; ncl.y = nc[1]; ncl.z = nc[2]; ncl.w = nc[3];

    reinterpret_cast<float4*>(out)[g]     = hid;   // new_hidden
    reinterpret_cast<float4*>(out + H)[g] = ncl;   // new_cell

    // Last epilogue block resets all cross-launch state for graph replay.
    __syncthreads();
    if (t == 0) {
        unsigned int prev = atomicAdd(&g_done, 1u);
        if (prev == EBLOCKS - 1) {
            g_ready = 0; g_cnt = 0; g_done = 0;
            g_csum = 0.f; g_csumsq = 0.f;
            #pragma unroll
            for (int p = 0; p < 5; p++) { g_sum[p] = 0.f; g_sumsq[p] = 0.f; }
        }
    }
}

// ---------------------------------------------------------------------------
// Launch: fork/join, GEMV submitted FIRST on stream 0 (identical to the
// passing R11 shape). The ONLY delta vs R11: the epilogue's stream is created
// with the highest priority so the work distributor schedules its 16 blocks
// into freed slots during (not after) the GEMV.
// Inputs (metadata order): 0=h0, 1=c0, 2=h1, 3=c1, 4=W,
//   5=ffio_g(4H), 6=ffio_b(4H), 7=u_g, 8=u_b, 9=c_g, 10=c_b
// Output: [new_hidden(4096); new_cell(4096)] fp32
// ---------------------------------------------------------------------------
extern "C" void kernel_launch(void* const* d_in, const int* in_sizes, int n_in,
                              void* d_out, int out_size)
{
    const float* h0     = (const float*)d_in[0];
    const float* c0     = (const float*)d_in[1];
    const float* h1     = (const float*)d_in[2];
    const float* c1     = (const float*)d_in[3];
    const float* W      = (const float*)d_in[4];
    const float* ffio_g = (const float*)d_in[5];
    const float* ffio_b = (const float*)d_in[6];
    const float* u_g    = (const float*)d_in[7];
    const float* u_b    = (const float*)d_in[8];
    const float* c_g    = (const float*)d_in[9];
    const float* c_b    = (const float*)d_in[10];
    float* out = (float*)d_out;

    cudaStream_t s2;
    cudaEvent_t ev_fork, ev_join;
    // Highest priority (runtime clamps out-of-range values to the valid range).
    cudaStreamCreateWithPriority(&s2, cudaStreamNonBlocking, -5);
    cudaEventCreateWithFlags(&ev_fork, cudaEventDisableTiming);
    cudaEventCreateWithFlags(&ev_join, cudaEventDisableTiming);

    // Fork: bring s2 into the captured graph.
    cudaEventRecord(ev_fork, 0);
    cudaStreamWaitEvent(s2, ev_fork, 0);

    gemv_kernel<<<NGEMV, 256>>>(h0, h1, W);                       // stream 0
    epilogue_kernel<<<EBLOCKS, ETHR, 0, s2>>>(c0, c1, ffio_g, ffio_b,
                                              u_g, u_b, c_g, c_b, out);

    // Join back to the main stream.
    cudaEventRecord(ev_join, s2);
    cudaStreamWaitEvent(0, ev_join, 0);
}

// round 14
// speedup vs baseline: 1.0104x; 1.0104x over previous
#include <cuda_runtime.h>
#include <math.h>

#define H 4096
#define EPS 1e-5f
#define ROWS_PER_BLOCK 8
#define NGEMV (5 * H / ROWS_PER_BLOCK)   // 2560 blocks, 512 per z-part
#define EBLOCKS 16                        // blocks 0..15 are dual-role

// Scratch + accumulators (no device allocation allowed).
__device__ __align__(16) float g_z[5 * H];
__device__ float g_sum[5]   = {0.f, 0.f, 0.f, 0.f, 0.f};
__device__ float g_sumsq[5] = {0.f, 0.f, 0.f, 0.f, 0.f};
__device__ float g_csum   = 0.f;
__device__ float g_csumsq = 0.f;
__device__ unsigned int g_ready = 0;   // gemv blocks completed
__device__ unsigned int g_cnt   = 0;   // epilogue blocks at cell-LN barrier
__device__ unsigned int g_done  = 0;   // epilogue blocks finished

__device__ __forceinline__ float sigmoidf_(float x) {
    return 1.0f / (1.0f + __expf(-x));
}
// tanh(x) = 1 - 2/(exp(2x)+1); saturates correctly at +/-inf.
__device__ __forceinline__ float tanhf_(float x) {
    return 1.0f - 2.0f / (__expf(2.0f * x) + 1.0f);
}

// ---------------------------------------------------------------------------
// One kernel. ALL 2560 blocks run the proven GEMV (one warp per row, x staged
// in shared, W streamed with __ldcs) and signal g_ready. Blocks 0..15 — which
// are resident from wave 1 — then prefetch the epilogue parameters (scalar,
// overlapping the remaining ~77us of the W stream), spin for g_ready==2560,
// and run an all-scalar epilogue: thread (b,t) owns element e = b*256+t of
// every 4096-wide vector. Cross-block cell-LN stats via atomics + counter.
// Every shared array is 16B-aligned; the epilogue path does NO vector loads.
// ---------------------------------------------------------------------------
__global__ __launch_bounds__(256, 4)
void fused_kernel(const float* __restrict__ h0,
                  const float* __restrict__ h1,
                  const float* __restrict__ W,
                  const float* __restrict__ c0,
                  const float* __restrict__ c1,
                  const float* __restrict__ ffio_g,
                  const float* __restrict__ ffio_b,
                  const float* __restrict__ u_g,
                  const float* __restrict__ u_b,
                  const float* __restrict__ c_g,
                  const float* __restrict__ c_b,
                  float* __restrict__ out)
{
    __shared__ __align__(16) float xs[2 * H];
    __shared__ __align__(16) float rs[8];
    __shared__ __align__(16) float rq[8];
    __shared__ __align__(16) float red_s[8];
    __shared__ __align__(16) float red_q[8];
    __shared__ float s_mc, s_rc;

    const int tid  = threadIdx.x;
    const int warp = tid >> 5;
    const int lane = tid & 31;

    // ================= GEMV (all blocks) =================
    {
        const float4* h0v = reinterpret_cast<const float4*>(h0);
        const float4* h1v = reinterpret_cast<const float4*>(h1);
        float4* xsv = reinterpret_cast<float4*>(xs);
        #pragma unroll
        for (int i = tid; i < H / 4; i += 256) {
            xsv[i]         = h0v[i];
            xsv[i + H / 4] = h1v[i];
        }
        __syncthreads();

        const int row = blockIdx.x * ROWS_PER_BLOCK + warp;
        const float4* wrow =
            reinterpret_cast<const float4*>(W + (size_t)row * (2 * H));

        float a0 = 0.f, a1 = 0.f, a2 = 0.f, a3 = 0.f;
        #pragma unroll 8
        for (int i = lane; i < (2 * H) / 4; i += 32) {
            float4 w = __ldcs(&wrow[i]);
            float4 x = xsv[i];
            a0 = fmaf(w.x, x.x, a0);
            a1 = fmaf(w.y, x.y, a1);
            a2 = fmaf(w.z, x.z, a2);
            a3 = fmaf(w.w, x.w, a3);
        }
        float s = (a0 + a1) + (a2 + a3);
        #pragma unroll
        for (int off = 16; off > 0; off >>= 1)
            s += __shfl_down_sync(0xffffffffu, s, off);

        if (lane == 0) {
            g_z[row] = s;
            rs[warp] = s;
            rq[warp] = s * s;
        }
        __syncthreads();

        if (tid == 0) {
            float bs = 0.f, bq = 0.f;
            #pragma unroll
            for (int w = 0; w < 8; w++) { bs += rs[w]; bq += rq[w]; }
            const int part = blockIdx.x >> 9;     // 512 blocks per part
            atomicAdd(&g_sum[part],   bs);
            atomicAdd(&g_sumsq[part], bq);
            __threadfence();                      // release: z-stores + stats
            atomicAdd(&g_ready, 1u);              // before the ready signal
        }
    }

    if (blockIdx.x >= EBLOCKS) return;

    // ================= Epilogue (blocks 0..15, resident from wave 1) ========
    const int e = blockIdx.x * 256 + tid;         // element 0..4095

    // ---- Scalar prefetch of GEMV-independent params (overlaps the stream) --
    const float fg0 = ffio_g[0 * H + e], fb0 = ffio_b[0 * H + e];
    const float fg1 = ffio_g[1 * H + e], fb1 = ffio_b[1 * H + e];
    const float fg2 = ffio_g[2 * H + e], fb2 = ffio_b[2 * H + e];
    const float fg3 = ffio_g[3 * H + e], fb3 = ffio_b[3 * H + e];
    const float ug  = u_g[e],  ub  = u_b[e];
    const float c0e = c0[e],   c1e = c1[e];
    const float cge = c_g[e],  cbe = c_b[e];

    // ---- Acquire: wait for all 2560 gemv blocks -----------------------------
    if (tid == 0) {
        while (*((volatile unsigned int*)&g_ready) < (unsigned)NGEMV)
            __nanosleep(64);
    }
    __syncthreads();
    __threadfence();

    // Part statistics (L2, bypass L1).
    float m5[5], r5[5];
    #pragma unroll
    for (int p = 0; p < 5; p++) {
        float su = __ldcg(&g_sum[p]);
        float sq = __ldcg(&g_sumsq[p]);
        float mean = su * (1.0f / H);
        float var  = sq * (1.0f / H) - mean * mean;
        m5[p] = mean;
        r5[p] = rsqrtf(var + EPS);
    }

    // z values (scalar, L2-hot — written by this launch's gemv blocks).
    const float z0 = __ldcg(&g_z[0 * H + e]);
    const float z1 = __ldcg(&g_z[1 * H + e]);
    const float z2 = __ldcg(&g_z[2 * H + e]);
    const float z3 = __ldcg(&g_z[3 * H + e]);
    const float z4 = __ldcg(&g_z[4 * H + e]);

    const float f0 = sigmoidf_(fmaf((z0 - m5[0]) * r5[0], fg0, fb0));
    const float f1 = sigmoidf_(fmaf((z1 - m5[1]) * r5[1], fg1, fb1));
    const float gi = sigmoidf_(fmaf((z2 - m5[2]) * r5[2], fg2, fb2));
    const float go = sigmoidf_(fmaf((z3 - m5[3]) * r5[3], fg3, fb3));
    const float uu = tanhf_  (fmaf((z4 - m5[4]) * r5[4], ug,  ub));

    const float cell = fmaf(gi, uu, fmaf(f0, c0e, f1 * c1e));

    // Block partial (sum, sumsq) of cell
    {
        float s = cell;
        float q = cell * cell;
        #pragma unroll
        for (int off = 16; off > 0; off >>= 1) {
            s += __shfl_down_sync(0xffffffffu, s, off);
            q += __shfl_down_sync(0xffffffffu, q, off);
        }
        if (lane == 0) { red_s[warp] = s; red_q[warp] = q; }
    }
    __syncthreads();

    // Cross-block (16 blocks) cell-LN reduction.
    if (tid == 0) {
        float bs = 0.f, bq = 0.f;
        #pragma unroll
        for (int w = 0; w < 8; w++) { bs += red_s[w]; bq += red_q[w]; }
        atomicAdd(&g_csum,   bs);
        atomicAdd(&g_csumsq, bq);
        __threadfence();
        atomicAdd(&g_cnt, 1u);
        while (*((volatile unsigned int*)&g_cnt) < EBLOCKS)
            __nanosleep(32);
        __threadfence();
        float cs = atomicAdd(&g_csum,   0.0f);
        float cq = atomicAdd(&g_csumsq, 0.0f);
        float mean = cs * (1.0f / H);
        float var  = cq * (1.0f / H) - mean * mean;
        s_mc = mean;
        s_rc = rsqrtf(var + EPS);
    }
    __syncthreads();

    // Final LN on cell + outputs (scalar, coalesced)
    const float ncell = fmaf((cell - s_mc) * s_rc, cge, cbe);
    out[e]     = go * tanhf_(ncell);   // new_hidden
    out[H + e] = ncell;                // new_cell

    // Last epilogue block resets all cross-launch state for graph replay.
    __syncthreads();
    if (tid == 0) {
        unsigned int prev = atomicAdd(&g_done, 1u);
        if (prev == EBLOCKS - 1) {
            g_ready = 0; g_cnt = 0; g_done = 0;
            g_csum = 0.f; g_csumsq = 0.f;
            #pragma unroll
            for (int p = 0; p < 5; p++) { g_sum[p] = 0.f; g_sumsq[p] = 0.f; }
        }
    }
}

// ---------------------------------------------------------------------------
// Inputs (metadata order): 0=h0, 1=c0, 2=h1, 3=c1, 4=W,
//   5=ffio_g(4H), 6=ffio_b(4H), 7=u_g, 8=u_b, 9=c_g, 10=c_b
// Output: [new_hidden(4096); new_cell(4096)] fp32
// ---------------------------------------------------------------------------
extern "C" void kernel_launch(void* const* d_in, const int* in_sizes, int n_in,
                              void* d_out, int out_size)
{
    const float* h0     = (const float*)d_in[0];
    const float* c0     = (const float*)d_in[1];
    const float* h1     = (const float*)d_in[2];
    const float* c1     = (const float*)d_in[3];
    const float* W      = (const float*)d_in[4];
    const float* ffio_g = (const float*)d_in[5];
    const float* ffio_b = (const float*)d_in[6];
    const float* u_g    = (const float*)d_in[7];
    const float* u_b    = (const float*)d_in[8];
    const float* c_g    = (const float*)d_in[9];
    const float* c_b    = (const float*)d_in[10];
    float* out = (float*)d_out;

    fused_kernel<<<NGEMV, 256>>>(h0, h1, W, c0, c1,
                                 ffio_g, ffio_b, u_g, u_b, c_g, c_b, out);
}

// round 15
// speedup vs baseline: 1.0156x; 1.0051x over previous
#include <cuda_runtime.h>
#include <math.h>

#define H 4096
#define EPS 1e-5f
#define ROWS_PER_BLOCK 8
#define NGEMV (5 * H / ROWS_PER_BLOCK)   // 2560 blocks, 512 per z-part
#define EBLOCKS 8                         // blocks 0..7 are dual-role
#define EPT 2                             // elements per epilogue thread

// Scratch + accumulators (no device allocation allowed).
__device__ __align__(16) float g_z[5 * H];
__device__ float g_sum[5]   = {0.f, 0.f, 0.f, 0.f, 0.f};
__device__ float g_sumsq[5] = {0.f, 0.f, 0.f, 0.f, 0.f};
__device__ float g_csum   = 0.f;
__device__ float g_csumsq = 0.f;
__device__ unsigned int g_ready = 0;   // gemv blocks completed
__device__ unsigned int g_cnt   = 0;   // epilogue blocks at cell-LN barrier
__device__ unsigned int g_done  = 0;   // epilogue blocks finished

__device__ __forceinline__ float sigmoidf_(float x) {
    return 1.0f / (1.0f + __expf(-x));
}
// tanh(x) = 1 - 2/(exp(2x)+1); saturates correctly at +/-inf.
__device__ __forceinline__ float tanhf_(float x) {
    return 1.0f - 2.0f / (__expf(2.0f * x) + 1.0f);
}

// ---------------------------------------------------------------------------
// One kernel. ALL 2560 blocks run the proven GEMV (one warp per row, x staged
// in shared, W streamed with __ldcs) and signal g_ready. Blocks 0..7 — which
// are resident from wave 1 — then prefetch the epilogue parameters (scalar,
// 2 elements/thread, overlapping the remaining ~80us of the W stream), spin
// for g_ready==2560, and run an all-scalar epilogue.
// Every shared array is 16B-aligned; the epilogue path does NO vector loads.
// ---------------------------------------------------------------------------
__global__ __launch_bounds__(256, 4)
void fused_kernel(const float* __restrict__ h0,
                  const float* __restrict__ h1,
                  const float* __restrict__ W,
                  const float* __restrict__ c0,
                  const float* __restrict__ c1,
                  const float* __restrict__ ffio_g,
                  const float* __restrict__ ffio_b,
                  const float* __restrict__ u_g,
                  const float* __restrict__ u_b,
                  const float* __restrict__ c_g,
                  const float* __restrict__ c_b,
                  float* __restrict__ out)
{
    __shared__ __align__(16) float xs[2 * H];
    __shared__ __align__(16) float rs[8];
    __shared__ __align__(16) float rq[8];
    __shared__ __align__(16) float red_s[8];
    __shared__ __align__(16) float red_q[8];
    __shared__ float s_mc, s_rc;

    const int tid  = threadIdx.x;
    const int warp = tid >> 5;
    const int lane = tid & 31;

    // ================= GEMV (all blocks) =================
    {
        const float4* h0v = reinterpret_cast<const float4*>(h0);
        const float4* h1v = reinterpret_cast<const float4*>(h1);
        float4* xsv = reinterpret_cast<float4*>(xs);
        #pragma unroll
        for (int i = tid; i < H / 4; i += 256) {
            xsv[i]         = h0v[i];
            xsv[i + H / 4] = h1v[i];
        }
        __syncthreads();

        const int row = blockIdx.x * ROWS_PER_BLOCK + warp;
        const float4* wrow =
            reinterpret_cast<const float4*>(W + (size_t)row * (2 * H));

        float a0 = 0.f, a1 = 0.f, a2 = 0.f, a3 = 0.f;
        #pragma unroll 8
        for (int i = lane; i < (2 * H) / 4; i += 32) {
            float4 w = __ldcs(&wrow[i]);
            float4 x = xsv[i];
            a0 = fmaf(w.x, x.x, a0);
            a1 = fmaf(w.y, x.y, a1);
            a2 = fmaf(w.z, x.z, a2);
            a3 = fmaf(w.w, x.w, a3);
        }
        float s = (a0 + a1) + (a2 + a3);
        #pragma unroll
        for (int off = 16; off > 0; off >>= 1)
            s += __shfl_down_sync(0xffffffffu, s, off);

        if (lane == 0) {
            g_z[row] = s;
            rs[warp] = s;
            rq[warp] = s * s;
        }
        __syncthreads();

        if (tid == 0) {
            float bs = 0.f, bq = 0.f;
            #pragma unroll
            for (int w = 0; w < 8; w++) { bs += rs[w]; bq += rq[w]; }
            const int part = blockIdx.x >> 9;     // 512 blocks per part
            atomicAdd(&g_sum[part],   bs);
            atomicAdd(&g_sumsq[part], bq);
            __threadfence();                      // release: z-stores + stats
            atomicAdd(&g_ready, 1u);              // before the ready signal
        }
    }

    if (blockIdx.x >= EBLOCKS) return;

    // ================= Epilogue (blocks 0..7, resident from wave 1) =========
    // Thread owns elements e[j] = blockIdx*512 + tid + 256*j, j=0..1.
    int e[EPT];
    #pragma unroll
    for (int j = 0; j < EPT; j++) e[j] = blockIdx.x * (256 * EPT) + tid + 256 * j;

    // ---- Scalar prefetch of GEMV-independent params (overlaps the stream) --
    float fg0[EPT], fb0[EPT], fg1[EPT], fb1[EPT];
    float fg2[EPT], fb2[EPT], fg3[EPT], fb3[EPT];
    float ug[EPT], ub[EPT], c0e[EPT], c1e[EPT], cge[EPT], cbe[EPT];
    #pragma unroll
    for (int j = 0; j < EPT; j++) {
        fg0[j] = ffio_g[0 * H + e[j]]; fb0[j] = ffio_b[0 * H + e[j]];
        fg1[j] = ffio_g[1 * H + e[j]]; fb1[j] = ffio_b[1 * H + e[j]];
        fg2[j] = ffio_g[2 * H + e[j]]; fb2[j] = ffio_b[2 * H + e[j]];
        fg3[j] = ffio_g[3 * H + e[j]]; fb3[j] = ffio_b[3 * H + e[j]];
        ug[j]  = u_g[e[j]];  ub[j]  = u_b[e[j]];
        c0e[j] = c0[e[j]];   c1e[j] = c1[e[j]];
        cge[j] = c_g[e[j]];  cbe[j] = c_b[e[j]];
    }

    // ---- Acquire: wait for all 2560 gemv blocks -----------------------------
    if (tid == 0) {
        while (*((volatile unsigned int*)&g_ready) < (unsigned)NGEMV)
            __nanosleep(64);
    }
    __syncthreads();
    __threadfence();

    // Part statistics (L2, bypass L1).
    float m5[5], r5[5];
    #pragma unroll
    for (int p = 0; p < 5; p++) {
        float su = __ldcg(&g_sum[p]);
        float sq = __ldcg(&g_sumsq[p]);
        float mean = su * (1.0f / H);
        float var  = sq * (1.0f / H) - mean * mean;
        m5[p] = mean;
        r5[p] = rsqrtf(var + EPS);
    }

    float cell[EPT], go[EPT];
    float s_part = 0.f, q_part = 0.f;
    #pragma unroll
    for (int j = 0; j < EPT; j++) {
        const float z0 = __ldcg(&g_z[0 * H + e[j]]);
        const float z1 = __ldcg(&g_z[1 * H + e[j]]);
        const float z2 = __ldcg(&g_z[2 * H + e[j]]);
        const float z3 = __ldcg(&g_z[3 * H + e[j]]);
        const float z4 = __ldcg(&g_z[4 * H + e[j]]);

        const float f0 = sigmoidf_(fmaf((z0 - m5[0]) * r5[0], fg0[j], fb0[j]));
        const float f1 = sigmoidf_(fmaf((z1 - m5[1]) * r5[1], fg1[j], fb1[j]));
        const float gi = sigmoidf_(fmaf((z2 - m5[2]) * r5[2], fg2[j], fb2[j]));
        go[j]          = sigmoidf_(fmaf((z3 - m5[3]) * r5[3], fg3[j], fb3[j]));
        const float uu = tanhf_  (fmaf((z4 - m5[4]) * r5[4], ug[j],  ub[j]));

        cell[j] = fmaf(gi, uu, fmaf(f0, c0e[j], f1 * c1e[j]));
        s_part += cell[j];
        q_part  = fmaf(cell[j], cell[j], q_part);
    }

    // Block partial (sum, sumsq) of cell
    {
        float s = s_part, q = q_part;
        #pragma unroll
        for (int off = 16; off > 0; off >>= 1) {
            s += __shfl_down_sync(0xffffffffu, s, off);
            q += __shfl_down_sync(0xffffffffu, q, off);
        }
        if (lane == 0) { red_s[warp] = s; red_q[warp] = q; }
    }
    __syncthreads();

    // Cross-block (8 blocks) cell-LN reduction.
    if (tid == 0) {
        float bs = 0.f, bq = 0.f;
        #pragma unroll
        for (int w = 0; w < 8; w++) { bs += red_s[w]; bq += red_q[w]; }
        atomicAdd(&g_csum,   bs);
        atomicAdd(&g_csumsq, bq);
        __threadfence();
        atomicAdd(&g_cnt, 1u);
        while (*((volatile unsigned int*)&g_cnt) < EBLOCKS)
            __nanosleep(32);
        __threadfence();
        float cs = atomicAdd(&g_csum,   0.0f);
        float cq = atomicAdd(&g_csumsq, 0.0f);
        float mean = cs * (1.0f / H);
        float var  = cq * (1.0f / H) - mean * mean;
        s_mc = mean;
        s_rc = rsqrtf(var + EPS);
    }
    __syncthreads();

    // Final LN on cell + outputs (scalar, coalesced)
    const float mc = s_mc, rc = s_rc;
    #pragma unroll
    for (int j = 0; j < EPT; j++) {
        const float ncell = fmaf((cell[j] - mc) * rc, cge[j], cbe[j]);
        out[e[j]]     = go[j] * tanhf_(ncell);   // new_hidden
        out[H + e[j]] = ncell;                   // new_cell
    }

    // Last epilogue block resets all cross-launch state for graph replay.
    __syncthreads();
    if (tid == 0) {
        unsigned int prev = atomicAdd(&g_done, 1u);
        if (prev == EBLOCKS - 1) {
            g_ready = 0; g_cnt = 0; g_done = 0;
            g_csum = 0.f; g_csumsq = 0.f;
            #pragma unroll
            for (int p = 0; p < 5; p++) { g_sum[p] = 0.f; g_sumsq[p] = 0.f; }
        }
    }
}

// ---------------------------------------------------------------------------
// Inputs (metadata order): 0=h0, 1=c0, 2=h1, 3=c1, 4=W,
//   5=ffio_g(4H), 6=ffio_b(4H), 7=u_g, 8=u_b, 9=c_g, 10=c_b
// Output: [new_hidden(4096); new_cell(4096)] fp32
// ---------------------------------------------------------------------------
extern "C" void kernel_launch(void* const* d_in, const int* in_sizes, int n_in,
                              void* d_out, int out_size)
{
    const float* h0     = (const float*)d_in[0];
    const float* c0     = (const float*)d_in[1];
    const float* h1     = (const float*)d_in[2];
    const float* c1     = (const float*)d_in[3];
    const float* W      = (const float*)d_in[4];
    const float* ffio_g = (const float*)d_in[5];
    const float* ffio_b = (const float*)d_in[6];
    const float* u_g    = (const float*)d_in[7];
    const float* u_b    = (const float*)d_in[8];
    const float* c_g    = (const float*)d_in[9];
    const float* c_b    = (const float*)d_in[10];
    float* out = (float*)d_out;

    fused_kernel<<<NGEMV, 256>>>(h0, h1, W, c0, c1,
                                 ffio_g, ffio_b, u_g, u_b, c_g, c_b, out);
}